// round 2
// baseline (speedup 1.0000x reference)
#include <cuda_runtime.h>
#include <math.h>

// Problem constants (fixed by reference setup_inputs)
#define B_DIM 32
#define S_DIM 512
#define A_DIM 8
#define L_DIM 32
#define E_DIM 256
#define STILE 32
#define NBLK_X (S_DIM / STILE)          // 16
#define NBLK   (B_DIM * NBLK_X)         // 512

#define IGNORE_INDEX (-100)
#define TAG_O 1

// Block partial sums: [conf_sum, cls_nll_sum, cls_count, reg_se_sum, pos_count]
__device__ float g_part[NBLK][5];

__global__ __launch_bounds__(256, 4)
void loss_main(const int*   __restrict__ input_len,
               const float* __restrict__ conf_logits,
               const float* __restrict__ cls_logits,
               const float* __restrict__ reg_logits,
               const float* __restrict__ label,
               const int*   __restrict__ index,
               const float* __restrict__ anchors,
               const float* __restrict__ thr_pos_p,
               const float* __restrict__ thr_neg_p)
{
    const int b    = blockIdx.y;
    const int tile = blockIdx.x;
    const int t    = threadIdx.x;

    __shared__ float s_ll[E_DIM];
    __shared__ float s_lr[E_DIM];
    __shared__ int   s_ty[E_DIM];
    __shared__ int   s_warp_cnt[8];
    __shared__ float s_red[8][5];

    // ---- Order-preserving compaction of this batch's entities (E == blockDim) ----
    {
        const int e    = t;
        const int mine = (index[e] == b) ? 1 : 0;
        const unsigned mask = __ballot_sync(0xffffffffu, mine);
        const int lane = t & 31;
        const int w    = t >> 5;
        if (lane == 0) s_warp_cnt[w] = __popc(mask);
        // stage the entity data while counts propagate
        float ty = 0.f, ll = 0.f, lr = 0.f;
        if (mine) {
            ty = label[e * 3 + 0];
            ll = label[e * 3 + 1];
            lr = label[e * 3 + 2];
        }
        __syncthreads();
        int base = 0;
        #pragma unroll
        for (int i = 0; i < 8; i++) if (i < w) base += s_warp_cnt[i];
        if (mine) {
            const int off = base + __popc(mask & ((1u << lane) - 1u));
            s_ty[off] = (int)ty;
            s_ll[off] = ll;
            s_lr[off] = lr;
        }
        __syncthreads();
    }
    int cnt = 0;
    #pragma unroll
    for (int i = 0; i < 8; i++) cnt += s_warp_cnt[i];

    // ---- Anchor assignment ----
    const int s_idx = tile * STILE + (t >> 3);
    const int a     = t & 7;

    const float ac  = anchors[(s_idx * A_DIM + a) * 2 + 0];
    const float asz = anchors[(s_idx * A_DIM + a) * 2 + 1];
    const float al  = ac - asz * 0.5f;
    const float ar  = ac + asz * 0.5f;

    const float thr_pos = thr_pos_p[0];
    const float thr_neg = thr_neg_p[0];
    const int   len_b   = input_len[b];

    // ---- IOU max / argmax over this batch's entities (reference op order) ----
    float best = -1.0f;
    int   bk   = 0;
    for (int k = 0; k < cnt; k++) {
        const float ll = s_ll[k];
        const float lr = s_lr[k];
        float inter = fminf(lr, ar) - fmaxf(ll, al);
        inter = fmaxf(inter, 0.0f);
        const float uni = (lr - ll) + (ar - al) - inter;
        const float iou = inter / uni;
        if (iou > best) { best = iou; bk = k; }   // strict > : first-max tie-break
    }

    const bool has_ent = (cnt > 0);
    const bool valid   = (s_idx < len_b);
    const bool active  = valid && has_ent;
    const bool pos     = active && (best >= thr_pos);
    const bool neg     = active && (best <= thr_neg);

    const size_t aidx = ((size_t)b * S_DIM + s_idx) * A_DIM + a;

    // ---- Confidence (BCE-with-logits, mean over ALL anchors) ----
    const float x  = conf_logits[aidx];
    const float sp = fmaxf(x, 0.0f) + log1pf(expf(-fabsf(x)));
    const float conf_term = sp - (pos ? x : 0.0f);

    // ---- Classification NLL where label != IGNORE ----
    float cls_nll = 0.0f, cls_c = 0.0f;
    if (pos || neg) {
        const int target = pos ? s_ty[bk] : TAG_O;
        const float4* row = (const float4*)(cls_logits + aidx * L_DIM);
        float m  = -INFINITY;
        float tv = 0.0f;
        float rr[L_DIM];
        #pragma unroll
        for (int i = 0; i < 8; i++) {
            const float4 q = row[i];
            rr[4*i+0] = q.x; rr[4*i+1] = q.y; rr[4*i+2] = q.z; rr[4*i+3] = q.w;
            m = fmaxf(m, fmaxf(fmaxf(q.x, q.y), fmaxf(q.z, q.w)));
            tv = (target == 4*i+0) ? q.x : tv;
            tv = (target == 4*i+1) ? q.y : tv;
            tv = (target == 4*i+2) ? q.z : tv;
            tv = (target == 4*i+3) ? q.w : tv;
        }
        float sum = 0.0f;
        #pragma unroll
        for (int i = 0; i < L_DIM; i++) sum += expf(rr[i] - m);
        cls_nll = -(tv - m - logf(sum));
        cls_c   = 1.0f;
    }

    // ---- Regression SE on positives only ----
    float reg_se = 0.0f, pos_c = 0.0f;
    if (pos) {
        const float ll = s_ll[bk];
        const float lr = s_lr[bk];
        const float lc = (ll + lr) * 0.5f;
        const float ls = lr - ll;
        const float oc = (lc - ac) / asz;
        const float os = ls / asz;
        const float r0 = reg_logits[aidx * 2 + 0];
        const float r1 = reg_logits[aidx * 2 + 1];
        reg_se = (r0 - oc) * (r0 - oc) + (r1 - os) * (r1 - os);
        pos_c  = 1.0f;
    }

    // ---- Deterministic block reduction (shuffle + smem, fixed order) ----
    float vals[5] = {conf_term, cls_nll, cls_c, reg_se, pos_c};
    #pragma unroll
    for (int j = 0; j < 5; j++) {
        float v = vals[j];
        #pragma unroll
        for (int off = 16; off > 0; off >>= 1)
            v += __shfl_down_sync(0xffffffffu, v, off);
        if ((t & 31) == 0) s_red[t >> 5][j] = v;
    }
    __syncthreads();
    if (t < 5) {
        float acc = 0.0f;
        #pragma unroll
        for (int w = 0; w < 8; w++) acc += s_red[w][t];
        g_part[blockIdx.y * gridDim.x + blockIdx.x][t] = acc;
    }
}

__global__ __launch_bounds__(256)
void loss_final(float* __restrict__ out)
{
    __shared__ float red[256];
    const int t = threadIdx.x;
    float acc[5];
    #pragma unroll
    for (int j = 0; j < 5; j++)
        acc[j] = g_part[t][j] + g_part[t + 256][j];

    float sums[5];
    for (int j = 0; j < 5; j++) {
        __syncthreads();
        red[t] = acc[j];
        __syncthreads();
        for (int off = 128; off > 0; off >>= 1) {
            if (t < off) red[t] += red[t + off];
            __syncthreads();
        }
        sums[j] = red[0];
    }
    if (t == 0) {
        const float conf_loss = sums[0] / (float)(B_DIM * S_DIM * A_DIM);
        const float cls_loss  = sums[1] / sums[2];
        const float reg_loss  = sums[3] / (sums[4] * 2.0f);
        const float total     = conf_loss + cls_loss + reg_loss;
        out[0] = total;
        out[1] = conf_loss;
        out[2] = cls_loss;
        out[3] = reg_loss;
    }
}

extern "C" void kernel_launch(void* const* d_in, const int* in_sizes, int n_in,
                              void* d_out, int out_size)
{
    const int*   input_len   = (const int*)  d_in[0];
    const float* conf_logits = (const float*)d_in[1];
    const float* cls_logits  = (const float*)d_in[2];
    const float* reg_logits  = (const float*)d_in[3];
    const float* label       = (const float*)d_in[4];
    const int*   index       = (const int*)  d_in[5];
    const float* anchors     = (const float*)d_in[6];
    const float* thr_pos     = (const float*)d_in[7];
    const float* thr_neg     = (const float*)d_in[8];
    float* out = (float*)d_out;

    dim3 grid(NBLK_X, B_DIM);
    loss_main<<<grid, 256>>>(input_len, conf_logits, cls_logits, reg_logits,
                             label, index, anchors, thr_pos, thr_neg);
    loss_final<<<1, 256>>>(out);
}

// round 3
// speedup vs baseline: 1.0888x; 1.0888x over previous
#include <cuda_runtime.h>
#include <math.h>

// Problem constants (fixed by reference setup_inputs)
#define B_DIM 32
#define S_DIM 512
#define A_DIM 8
#define L_DIM 32
#define E_DIM 256
#define STILE 32
#define NBLK_X (S_DIM / STILE)          // 16
#define NBLK   (B_DIM * NBLK_X)         // 512
#define TAG_O 1

// Block partial sums: [conf_sum, cls_nll_sum, cls_count, reg_se_sum, pos_count]
__device__ float    g_part[NBLK][5];
__device__ unsigned g_count = 0;

__device__ __forceinline__ float ldcg_f(const float* p) {
    float v;
    asm volatile("ld.global.cg.f32 %0, [%1];" : "=f"(v) : "l"(p));
    return v;
}

__global__ __launch_bounds__(256, 4)
void ssd_loss_fused(const int*   __restrict__ input_len,
                    const float* __restrict__ conf_logits,
                    const float* __restrict__ cls_logits,
                    const float* __restrict__ reg_logits,
                    const float* __restrict__ label,
                    const int*   __restrict__ index,
                    const float* __restrict__ anchors,
                    const float* __restrict__ thr_pos_p,
                    const float* __restrict__ thr_neg_p,
                    float*       __restrict__ out)
{
    const int b    = blockIdx.y;
    const int tile = blockIdx.x;
    const int t    = threadIdx.x;
    const int lane = t & 31;
    const int w    = t >> 5;

    __shared__ float4   s_cls[256][8];     // 32 KB, XOR-swizzled rows
    __shared__ float    s_ll[E_DIM];
    __shared__ float    s_lr[E_DIM];
    __shared__ int      s_ty[E_DIM];
    __shared__ int      s_warp_cnt[8];
    __shared__ float    s_red[8][5];
    __shared__ unsigned s_ticket;

    // ---- Stage this block's 256 cls rows (32 KB contiguous) coalesced ----
    {
        const float4* gcls = (const float4*)cls_logits;
        const size_t  base4 = ((size_t)b * S_DIM + (size_t)tile * STILE) * A_DIM * (L_DIM / 4);
        #pragma unroll
        for (int j = 0; j < 8; j++) {
            const int f = j * 256 + t;          // float4 index within tile
            const int r = f >> 3;
            const int c = f & 7;
            s_cls[r][c ^ (r & 7)] = gcls[base4 + f];
        }
    }

    // ---- Order-preserving compaction of this batch's entities ----
    {
        const int mine = (index[t] == b) ? 1 : 0;
        const unsigned mask = __ballot_sync(0xffffffffu, mine);
        if (lane == 0) s_warp_cnt[w] = __popc(mask);
        float ty = 0.f, ll = 0.f, lr = 0.f;
        if (mine) {
            ty = label[t * 3 + 0];
            ll = label[t * 3 + 1];
            lr = label[t * 3 + 2];
        }
        __syncthreads();
        int base = 0;
        #pragma unroll
        for (int i = 0; i < 8; i++) if (i < w) base += s_warp_cnt[i];
        if (mine) {
            const int off = base + __popc(mask & ((1u << lane) - 1u));
            s_ty[off] = (int)ty;
            s_ll[off] = ll;
            s_lr[off] = lr;
        }
        __syncthreads();
    }
    int cnt = 0;
    #pragma unroll
    for (int i = 0; i < 8; i++) cnt += s_warp_cnt[i];

    // ---- Anchor assignment ----
    const int s_idx = tile * STILE + (t >> 3);
    const int a     = t & 7;

    const float ac  = anchors[(s_idx * A_DIM + a) * 2 + 0];
    const float asz = anchors[(s_idx * A_DIM + a) * 2 + 1];
    const float al  = ac - asz * 0.5f;
    const float ar  = ac + asz * 0.5f;

    const float thr_pos = thr_pos_p[0];
    const float thr_neg = thr_neg_p[0];
    const int   len_b   = input_len[b];

    // ---- IOU max / argmax (reference op order, strict > = first-max) ----
    float best = -1.0f;
    int   bk   = 0;
    for (int k = 0; k < cnt; k++) {
        const float ll = s_ll[k];
        const float lr = s_lr[k];
        float inter = fminf(lr, ar) - fmaxf(ll, al);
        inter = fmaxf(inter, 0.0f);
        const float uni = (lr - ll) + (ar - al) - inter;
        const float iou = inter / uni;
        if (iou > best) { best = iou; bk = k; }
    }

    const bool has_ent = (cnt > 0);
    const bool valid   = (s_idx < len_b);
    const bool active  = valid && has_ent;
    const bool pos     = active && (best >= thr_pos);
    const bool neg     = active && (best <= thr_neg);

    const size_t aidx = ((size_t)b * S_DIM + s_idx) * A_DIM + a;

    // ---- Confidence (BCE-with-logits, mean over ALL anchors) ----
    const float x  = conf_logits[aidx];
    const float sp = fmaxf(x, 0.0f) + log1pf(expf(-fabsf(x)));
    const float conf_term = sp - (pos ? x : 0.0f);

    // ---- Classification NLL from smem (two passes, conflict-free LDS.128) ----
    float cls_nll = 0.0f, cls_c = 0.0f;
    if (pos || neg) {
        const int target = pos ? s_ty[bk] : TAG_O;
        const int ti = target >> 2;   // which float4
        const int tc = target & 3;    // which component
        float m  = -INFINITY;
        float tv = 0.0f;
        #pragma unroll
        for (int i = 0; i < 8; i++) {
            const float4 q = s_cls[t][i ^ (t & 7)];
            m = fmaxf(m, fmaxf(fmaxf(q.x, q.y), fmaxf(q.z, q.w)));
            if (i == ti) tv = (tc == 0) ? q.x : (tc == 1) ? q.y : (tc == 2) ? q.z : q.w;
        }
        float sum = 0.0f;
        #pragma unroll
        for (int i = 0; i < 8; i++) {
            const float4 q = s_cls[t][i ^ (t & 7)];
            sum += expf(q.x - m) + expf(q.y - m) + expf(q.z - m) + expf(q.w - m);
        }
        cls_nll = -(tv - m - logf(sum));
        cls_c   = 1.0f;
    }

    // ---- Regression SE on positives only ----
    float reg_se = 0.0f, pos_c = 0.0f;
    if (pos) {
        const float ll = s_ll[bk];
        const float lr = s_lr[bk];
        const float lc = (ll + lr) * 0.5f;
        const float ls = lr - ll;
        const float oc = (lc - ac) / asz;
        const float os = ls / asz;
        const float r0 = reg_logits[aidx * 2 + 0];
        const float r1 = reg_logits[aidx * 2 + 1];
        reg_se = (r0 - oc) * (r0 - oc) + (r1 - os) * (r1 - os);
        pos_c  = 1.0f;
    }

    // ---- Deterministic block reduction ----
    const int bid = b * NBLK_X + tile;
    {
        float vals[5] = {conf_term, cls_nll, cls_c, reg_se, pos_c};
        #pragma unroll
        for (int j = 0; j < 5; j++) {
            float v = vals[j];
            #pragma unroll
            for (int off = 16; off > 0; off >>= 1)
                v += __shfl_down_sync(0xffffffffu, v, off);
            if (lane == 0) s_red[w][j] = v;
        }
        __syncthreads();
        if (t < 5) {
            float acc = 0.0f;
            #pragma unroll
            for (int i = 0; i < 8; i++) acc += s_red[i][t];
            g_part[bid][t] = acc;
        }
    }

    // ---- Last-block-done final reduction (no second launch) ----
    __threadfence();
    __syncthreads();
    if (t == 0) s_ticket = atomicAdd(&g_count, 1u);
    __syncthreads();
    if (s_ticket != NBLK - 1) return;

    // This is the last block: all 512 partials are globally visible.
    float acc[5];
    #pragma unroll
    for (int j = 0; j < 5; j++)
        acc[j] = ldcg_f(&g_part[t][j]) + ldcg_f(&g_part[t + 256][j]);

    float sums[5];
    #pragma unroll
    for (int j = 0; j < 5; j++) {
        float v = acc[j];
        #pragma unroll
        for (int off = 16; off > 0; off >>= 1)
            v += __shfl_down_sync(0xffffffffu, v, off);
        if (lane == 0) s_red[w][j] = v;
    }
    __syncthreads();
    if (t == 0) {
        #pragma unroll
        for (int j = 0; j < 5; j++) {
            float s = 0.0f;
            #pragma unroll
            for (int i = 0; i < 8; i++) s += s_red[i][j];
            sums[j] = s;
        }
        const float conf_loss = sums[0] / (float)(B_DIM * S_DIM * A_DIM);
        const float cls_loss  = sums[1] / sums[2];
        const float reg_loss  = sums[3] / (sums[4] * 2.0f);
        out[0] = conf_loss + cls_loss + reg_loss;
        out[1] = conf_loss;
        out[2] = cls_loss;
        out[3] = reg_loss;
        atomicExch(&g_count, 0u);   // reset for next graph replay
    }
}

extern "C" void kernel_launch(void* const* d_in, const int* in_sizes, int n_in,
                              void* d_out, int out_size)
{
    const int*   input_len   = (const int*)  d_in[0];
    const float* conf_logits = (const float*)d_in[1];
    const float* cls_logits  = (const float*)d_in[2];
    const float* reg_logits  = (const float*)d_in[3];
    const float* label       = (const float*)d_in[4];
    const int*   index       = (const int*)  d_in[5];
    const float* anchors     = (const float*)d_in[6];
    const float* thr_pos     = (const float*)d_in[7];
    const float* thr_neg     = (const float*)d_in[8];
    float* out = (float*)d_out;

    dim3 grid(NBLK_X, B_DIM);
    ssd_loss_fused<<<grid, 256>>>(input_len, conf_logits, cls_logits, reg_logits,
                                  label, index, anchors, thr_pos, thr_neg, out);
}